// round 1
// baseline (speedup 1.0000x reference)
#include <cuda_runtime.h>
#include <cuda_bf16.h>
#include <math.h>

#define BN_ 4096      // batch
#define DD  128       // feature dim
#define HH  256       // hidden
#define TT  64        // time emb
#define KNN 10
#define NL  2
#define MSGIN 704     // 2H + D + T
#define NE  (BN_*KNN) // edges

// ---------------- static scratch ----------------
__device__ __align__(128) float g_x[BN_*DD];        // 2 MB
__device__ __align__(128) float g_dist[(size_t)BN_*BN_]; // 64 MB
__device__ __align__(128) int   g_idx[BN_*KNN];
__device__ __align__(128) float g_ew[BN_*KNN];
__device__ __align__(128) float g_s[BN_*HH];
__device__ __align__(128) float g_feat[(size_t)NE*MSGIN]; // ~115 MB
__device__ __align__(128) float g_h1[(size_t)NE*HH];      // ~42 MB
__device__ __align__(128) float g_msg[(size_t)NE*HH];     // ~42 MB
__device__ __align__(128) float g_agg[BN_*HH];
__device__ __align__(128) float g_cat[BN_*2*HH];
__device__ __align__(128) float g_u1[BN_*HH];

__device__ __forceinline__ float gelu_exact(float x) {
    return 0.5f * x * (1.0f + erff(x * 0.70710678118654752440f));
}

// ---------------- build x_flat ----------------
__global__ void build_x_kernel(const float* __restrict__ xc, const float* __restrict__ d0,
                               const float* __restrict__ d1, const float* __restrict__ d2,
                               const float* __restrict__ xo, float* __restrict__ X) {
    int i = blockIdx.x;
    int t = threadIdx.x; // 128
    float v;
    if (t < 64)       v = xc[i*64 + t];
    else if (t < 80)  v = d0[i*16 + (t-64)];
    else if (t < 96)  v = d1[i*16 + (t-80)];
    else if (t < 112) v = d2[i*16 + (t-96)];
    else              v = xo[i*16 + (t-112)];
    X[i*DD + t] = v;
}

// ---------------- L1 cdist, 128x128 tiles ----------------
__global__ __launch_bounds__(256) void cdist_kernel(const float* __restrict__ X,
                                                    float* __restrict__ Dist) {
    __shared__ float As[8][128];
    __shared__ float Bs[8][128];
    int bm = blockIdx.y * 128, bn = blockIdx.x * 128;
    int tid = threadIdx.x;
    int ty = tid >> 4, tx = tid & 15;
    float acc[8][8];
    #pragma unroll
    for (int i = 0; i < 8; i++)
        #pragma unroll
        for (int j = 0; j < 8; j++) acc[i][j] = 0.0f;

    for (int k0 = 0; k0 < DD; k0 += 8) {
        int m = tid >> 1, h = (tid & 1) * 4;
        float4 va = *(const float4*)&X[(size_t)(bm + m)*DD + k0 + h];
        As[h+0][m] = va.x; As[h+1][m] = va.y; As[h+2][m] = va.z; As[h+3][m] = va.w;
        float4 vb = *(const float4*)&X[(size_t)(bn + m)*DD + k0 + h];
        Bs[h+0][m] = vb.x; Bs[h+1][m] = vb.y; Bs[h+2][m] = vb.z; Bs[h+3][m] = vb.w;
        __syncthreads();
        #pragma unroll
        for (int k = 0; k < 8; k++) {
            float a[8], b[8];
            #pragma unroll
            for (int j = 0; j < 8; j++) a[j] = As[k][ty*8 + j];
            #pragma unroll
            for (int j = 0; j < 8; j++) b[j] = Bs[k][tx*8 + j];
            #pragma unroll
            for (int i = 0; i < 8; i++)
                #pragma unroll
                for (int j = 0; j < 8; j++) acc[i][j] += fabsf(a[i] - b[j]);
        }
        __syncthreads();
    }
    #pragma unroll
    for (int i = 0; i < 8; i++) {
        int row = bm + ty*8 + i;
        #pragma unroll
        for (int j = 0; j < 8; j++)
            Dist[(size_t)row*BN_ + bn + tx*8 + j] = acc[i][j];
    }
}

// ---------------- top-K + softmax edge weights ----------------
__global__ __launch_bounds__(256) void topk_kernel(const float* __restrict__ Dist,
                                                   int* __restrict__ Idx,
                                                   float* __restrict__ Ew) {
    int i = blockIdx.x;
    int tid = threadIdx.x;
    float best[KNN]; int bidx[KNN];
    #pragma unroll
    for (int q = 0; q < KNN; q++) { best[q] = 3.0e38f; bidx[q] = -1; }
    const float* row = Dist + (size_t)i * BN_;
    for (int j = tid; j < BN_; j += 256) {
        if (j == i) continue;
        float d = row[j];
        if (d < best[KNN-1]) {
            float dd = d; int ii = j;
            #pragma unroll
            for (int q = 0; q < KNN; q++) {
                if (dd < best[q]) {
                    float tb = best[q]; int ti = bidx[q];
                    best[q] = dd; bidx[q] = ii;
                    dd = tb; ii = ti;
                }
            }
        }
    }
    __shared__ float sd[256*KNN];
    __shared__ int   si[256*KNN];
    #pragma unroll
    for (int q = 0; q < KNN; q++) { sd[tid*KNN+q] = best[q]; si[tid*KNN+q] = bidx[q]; }
    __syncthreads();
    for (int stride = 128; stride >= 1; stride >>= 1) {
        if (tid < stride) {
            float* da = &sd[tid*KNN];        int* ia = &si[tid*KNN];
            float* db = &sd[(tid+stride)*KNN]; int* ib = &si[(tid+stride)*KNN];
            float od[KNN]; int oi[KNN];
            int pa = 0, pb = 0;
            #pragma unroll
            for (int q = 0; q < KNN; q++) {
                float va = da[pa], vb = db[pb];
                if (va <= vb) { od[q] = va; oi[q] = ia[pa]; pa++; }
                else          { od[q] = vb; oi[q] = ib[pb]; pb++; }
            }
            #pragma unroll
            for (int q = 0; q < KNN; q++) { da[q] = od[q]; ia[q] = oi[q]; }
        }
        __syncthreads();
    }
    if (tid == 0) {
        float w[KNN], sum = 0.0f;
        float dmin = sd[0];
        #pragma unroll
        for (int q = 0; q < KNN; q++) { w[q] = expf(dmin - sd[q]); sum += w[q]; }
        float inv = 1.0f / sum;
        #pragma unroll
        for (int q = 0; q < KNN; q++) {
            Ew[i*KNN + q] = w[q] * inv;
            Idx[i*KNN + q] = si[q];
        }
    }
}

// ---------------- generic SGEMM: C = act(A@W + bias) [+ Res], 128x128x8 ----------------
template<int DOGELU, int DORES>
__global__ __launch_bounds__(256) void sgemm_kernel(const float* __restrict__ A,
                                                    const float* __restrict__ W,
                                                    const float* __restrict__ bias,
                                                    const float* __restrict__ Res,
                                                    float* __restrict__ C,
                                                    int M, int N, int Kd) {
    __shared__ float As[8][128];
    __shared__ float Bs[8][128];
    int bm = blockIdx.y * 128, bn = blockIdx.x * 128;
    int tid = threadIdx.x;
    int ty = tid >> 4, tx = tid & 15;
    float acc[8][8];
    #pragma unroll
    for (int i = 0; i < 8; i++)
        #pragma unroll
        for (int j = 0; j < 8; j++) acc[i][j] = 0.0f;

    for (int k0 = 0; k0 < Kd; k0 += 8) {
        int m = tid >> 1, h = (tid & 1) * 4;
        float4 va = *(const float4*)&A[(size_t)(bm + m)*Kd + k0 + h];
        As[h+0][m] = va.x; As[h+1][m] = va.y; As[h+2][m] = va.z; As[h+3][m] = va.w;
        int kk = tid >> 5, n4 = (tid & 31) * 4;
        float4 vb = *(const float4*)&W[(size_t)(k0 + kk)*N + bn + n4];
        *(float4*)&Bs[kk][n4] = vb;
        __syncthreads();
        #pragma unroll
        for (int k = 0; k < 8; k++) {
            float a[8], b[8];
            #pragma unroll
            for (int j = 0; j < 8; j++) a[j] = As[k][ty*8 + j];
            #pragma unroll
            for (int j = 0; j < 8; j++) b[j] = Bs[k][tx*8 + j];
            #pragma unroll
            for (int i = 0; i < 8; i++)
                #pragma unroll
                for (int j = 0; j < 8; j++) acc[i][j] = fmaf(a[i], b[j], acc[i][j]);
        }
        __syncthreads();
    }
    #pragma unroll
    for (int i = 0; i < 8; i++) {
        int row = bm + ty*8 + i;
        #pragma unroll
        for (int j = 0; j < 8; j++) {
            int col = bn + tx*8 + j;
            float v = acc[i][j] + bias[col];
            if (DOGELU) v = gelu_exact(v);
            if (DORES)  v += Res[(size_t)row*N + col];
            C[(size_t)row*N + col] = v;
        }
    }
}

// ---------------- edge feature gather ----------------
__global__ void feat_kernel(const float* __restrict__ S, const float* __restrict__ X,
                            const float* __restrict__ Temb, const int* __restrict__ Idx,
                            float* __restrict__ F, long total) {
    long idx = (long)blockIdx.x * blockDim.x + threadIdx.x;
    if (idx >= total) return;
    int e = (int)(idx / MSGIN);
    int c = (int)(idx - (long)e * MSGIN);
    int i = e / KNN;
    int src = Idx[e];
    float v;
    if (c < 256)      v = S[src*HH + c];
    else if (c < 512) v = S[i*HH + (c-256)];
    else if (c < 640) v = X[src*DD + (c-512)] - X[i*DD + (c-512)];
    else              v = Temb[i*TT + (c-640)];
    F[idx] = v;
}

// ---------------- weighted segment sum (contiguous 10-edge groups) ----------------
__global__ void agg_kernel(const float* __restrict__ Msg, const float* __restrict__ Ew,
                           float* __restrict__ Agg) {
    int idx = blockIdx.x * blockDim.x + threadIdx.x; // B*H
    int i = idx >> 8;
    int h = idx & 255;
    float a = 0.0f;
    #pragma unroll
    for (int k = 0; k < KNN; k++)
        a = fmaf(Msg[(size_t)(i*KNN + k)*HH + h], Ew[i*KNN + k], a);
    Agg[idx] = a;
}

// ---------------- concat [s, agg] ----------------
__global__ void cat_kernel(const float* __restrict__ S, const float* __restrict__ Agg,
                           float* __restrict__ Cat) {
    int idx = blockIdx.x * blockDim.x + threadIdx.x; // B*512
    int i = idx >> 9;
    int c = idx & 511;
    Cat[idx] = (c < 256) ? S[i*HH + c] : Agg[i*HH + (c-256)];
}

// ---------------- center categorical blocks in-place ----------------
__global__ void center_kernel(float* __restrict__ Out) {
    int i = blockIdx.x;
    int t = threadIdx.x; // 48
    __shared__ float sv[48];
    float v = Out[i*DD + 64 + t];
    sv[t] = v;
    __syncthreads();
    int g = (t >> 4) << 4;
    float m = 0.0f;
    #pragma unroll
    for (int q = 0; q < 16; q++) m += sv[g + q];
    m *= (1.0f/16.0f);
    Out[i*DD + 64 + t] = v - m;
}

// ---------------- launcher ----------------
extern "C" void kernel_launch(void* const* d_in, const int* in_sizes, int n_in,
                              void* d_out, int out_size) {
    const float* x_c   = (const float*)d_in[0];
    const float* x_d0  = (const float*)d_in[1];
    const float* x_d1  = (const float*)d_in[2];
    const float* x_d2  = (const float*)d_in[3];
    const float* x_o   = (const float*)d_in[4];
    const float* t_emb = (const float*)d_in[5];
    const float* W_in  = (const float*)d_in[6];
    const float* b_in  = (const float*)d_in[7];
    const float* Wm1   = (const float*)d_in[8];
    const float* bm1   = (const float*)d_in[9];
    const float* Wm2   = (const float*)d_in[10];
    const float* bm2   = (const float*)d_in[11];
    const float* Wu1   = (const float*)d_in[12];
    const float* bu1   = (const float*)d_in[13];
    const float* Wu2   = (const float*)d_in[14];
    const float* bu2   = (const float*)d_in[15];
    const float* W_out = (const float*)d_in[16];
    const float* b_out = (const float*)d_in[17];
    float* out = (float*)d_out;

    float *x, *dist, *ew, *s, *feat, *h1, *msg, *agg, *cat, *u1;
    int* idx;
    cudaGetSymbolAddress((void**)&x,    g_x);
    cudaGetSymbolAddress((void**)&dist, g_dist);
    cudaGetSymbolAddress((void**)&idx,  g_idx);
    cudaGetSymbolAddress((void**)&ew,   g_ew);
    cudaGetSymbolAddress((void**)&s,    g_s);
    cudaGetSymbolAddress((void**)&feat, g_feat);
    cudaGetSymbolAddress((void**)&h1,   g_h1);
    cudaGetSymbolAddress((void**)&msg,  g_msg);
    cudaGetSymbolAddress((void**)&agg,  g_agg);
    cudaGetSymbolAddress((void**)&cat,  g_cat);
    cudaGetSymbolAddress((void**)&u1,   g_u1);

    build_x_kernel<<<BN_, 128>>>(x_c, x_d0, x_d1, x_d2, x_o, x);
    cdist_kernel<<<dim3(BN_/128, BN_/128), 256>>>(x, dist);
    topk_kernel<<<BN_, 256>>>(dist, idx, ew);

    // s = x @ W_in + b_in   (M=4096, N=256, K=128)
    sgemm_kernel<0,0><<<dim3(HH/128, BN_/128), 256>>>(x, W_in, b_in, nullptr, s, BN_, HH, DD);

    long feat_total = (long)NE * MSGIN;
    int  feat_blocks = (int)((feat_total + 255) / 256);

    for (int l = 0; l < NL; l++) {
        const float* wm1 = Wm1 + (size_t)l * MSGIN * HH;
        const float* wm2 = Wm2 + (size_t)l * HH * HH;
        const float* wu1 = Wu1 + (size_t)l * 2*HH * HH;
        const float* wu2 = Wu2 + (size_t)l * HH * HH;

        feat_kernel<<<feat_blocks, 256>>>(s, x, t_emb, idx, feat, feat_total);
        // h1 = gelu(feat @ Wm1 + bm1)  (M=40960, N=256, K=704)
        sgemm_kernel<1,0><<<dim3(HH/128, NE/128), 256>>>(feat, wm1, bm1 + l*HH, nullptr, h1, NE, HH, MSGIN);
        // msg = h1 @ Wm2 + bm2         (M=40960, N=256, K=256)
        sgemm_kernel<0,0><<<dim3(HH/128, NE/128), 256>>>(h1, wm2, bm2 + l*HH, nullptr, msg, NE, HH, HH);
        agg_kernel<<<BN_*HH/256, 256>>>(msg, ew, agg);
        cat_kernel<<<BN_*2*HH/256, 256>>>(s, agg, cat);
        // u1 = gelu(cat @ Wu1 + bu1)   (M=4096, N=256, K=512)
        sgemm_kernel<1,0><<<dim3(HH/128, BN_/128), 256>>>(cat, wu1, bu1 + l*HH, nullptr, u1, BN_, HH, 2*HH);
        // s = s + (u1 @ Wu2 + bu2)     (M=4096, N=256, K=256)
        sgemm_kernel<0,1><<<dim3(HH/128, BN_/128), 256>>>(u1, wu2, bu2 + l*HH, s, s, BN_, HH, HH);
    }

    // out = s @ W_out + b_out  (M=4096, N=128, K=256), then center cat blocks
    sgemm_kernel<0,0><<<dim3(DD/128, BN_/128), 256>>>(s, W_out, b_out, nullptr, out, BN_, DD, HH);
    center_kernel<<<BN_, 48>>>(out);
}

// round 2
// speedup vs baseline: 3.0343x; 3.0343x over previous
#include <cuda_runtime.h>
#include <cuda_bf16.h>
#include <math.h>

#define BN_ 4096      // batch
#define DD  128       // feature dim
#define HH  256       // hidden
#define TT  64        // time emb
#define KNN 10
#define NL  2

// ---------------- static scratch ----------------
__device__ __align__(128) float g_x[BN_*DD];             // 2 MB
__device__ __align__(128) float g_dist[(size_t)BN_*BN_]; // 64 MB
__device__ __align__(128) int   g_idx[BN_*KNN];
__device__ __align__(128) float g_ew[BN_*KNN];
__device__ __align__(128) float g_s[BN_*HH];
__device__ __align__(128) float g_pp[BN_*HH];
__device__ __align__(128) float g_qq[BN_*HH];
__device__ __align__(128) float g_aggh[BN_*HH];
__device__ __align__(128) float g_agg[BN_*HH];
__device__ __align__(128) float g_cat[BN_*2*HH];
__device__ __align__(128) float g_u1[BN_*HH];

__device__ __forceinline__ float gelu_exact(float x) {
    return 0.5f * x * (1.0f + erff(x * 0.70710678118654752440f));
}

// ---------------- build x_flat ----------------
__global__ void build_x_kernel(const float* __restrict__ xc, const float* __restrict__ d0,
                               const float* __restrict__ d1, const float* __restrict__ d2,
                               const float* __restrict__ xo, float* __restrict__ X) {
    int i = blockIdx.x;
    int t = threadIdx.x; // 128
    float v;
    if (t < 64)       v = xc[i*64 + t];
    else if (t < 80)  v = d0[i*16 + (t-64)];
    else if (t < 96)  v = d1[i*16 + (t-80)];
    else if (t < 112) v = d2[i*16 + (t-96)];
    else              v = xo[i*16 + (t-112)];
    X[i*DD + t] = v;
}

// ---------------- L1 cdist, 128x128 tiles ----------------
__global__ __launch_bounds__(256) void cdist_kernel(const float* __restrict__ X,
                                                    float* __restrict__ Dist) {
    __shared__ float As[8][128];
    __shared__ float Bs[8][128];
    int bm = blockIdx.y * 128, bn = blockIdx.x * 128;
    int tid = threadIdx.x;
    int ty = tid >> 4, tx = tid & 15;
    float acc[8][8];
    #pragma unroll
    for (int i = 0; i < 8; i++)
        #pragma unroll
        for (int j = 0; j < 8; j++) acc[i][j] = 0.0f;

    for (int k0 = 0; k0 < DD; k0 += 8) {
        int m = tid >> 1, h = (tid & 1) * 4;
        float4 va = *(const float4*)&X[(size_t)(bm + m)*DD + k0 + h];
        As[h+0][m] = va.x; As[h+1][m] = va.y; As[h+2][m] = va.z; As[h+3][m] = va.w;
        float4 vb = *(const float4*)&X[(size_t)(bn + m)*DD + k0 + h];
        Bs[h+0][m] = vb.x; Bs[h+1][m] = vb.y; Bs[h+2][m] = vb.z; Bs[h+3][m] = vb.w;
        __syncthreads();
        #pragma unroll
        for (int k = 0; k < 8; k++) {
            float a[8], b[8];
            #pragma unroll
            for (int j = 0; j < 8; j++) a[j] = As[k][ty*8 + j];
            #pragma unroll
            for (int j = 0; j < 8; j++) b[j] = Bs[k][tx*8 + j];
            #pragma unroll
            for (int i = 0; i < 8; i++)
                #pragma unroll
                for (int j = 0; j < 8; j++) acc[i][j] += fabsf(a[i] - b[j]);
        }
        __syncthreads();
    }
    #pragma unroll
    for (int i = 0; i < 8; i++) {
        int row = bm + ty*8 + i;
        #pragma unroll
        for (int j = 0; j < 8; j++)
            Dist[(size_t)row*BN_ + bn + tx*8 + j] = acc[i][j];
    }
}

// ---------------- top-K + softmax edge weights ----------------
__global__ __launch_bounds__(256) void topk_kernel(const float* __restrict__ Dist,
                                                   int* __restrict__ Idx,
                                                   float* __restrict__ Ew) {
    int i = blockIdx.x;
    int tid = threadIdx.x;
    float best[KNN]; int bidx[KNN];
    #pragma unroll
    for (int q = 0; q < KNN; q++) { best[q] = 3.0e38f; bidx[q] = -1; }
    const float* row = Dist + (size_t)i * BN_;
    for (int j = tid; j < BN_; j += 256) {
        if (j == i) continue;
        float d = row[j];
        if (d < best[KNN-1]) {
            float dd = d; int ii = j;
            #pragma unroll
            for (int q = 0; q < KNN; q++) {
                if (dd < best[q]) {
                    float tb = best[q]; int ti = bidx[q];
                    best[q] = dd; bidx[q] = ii;
                    dd = tb; ii = ti;
                }
            }
        }
    }
    __shared__ float sd[256*KNN];
    __shared__ int   si[256*KNN];
    #pragma unroll
    for (int q = 0; q < KNN; q++) { sd[tid*KNN+q] = best[q]; si[tid*KNN+q] = bidx[q]; }
    __syncthreads();
    for (int stride = 128; stride >= 1; stride >>= 1) {
        if (tid < stride) {
            float* da = &sd[tid*KNN];          int* ia = &si[tid*KNN];
            float* db = &sd[(tid+stride)*KNN]; int* ib = &si[(tid+stride)*KNN];
            float od[KNN]; int oi[KNN];
            int pa = 0, pb = 0;
            #pragma unroll
            for (int q = 0; q < KNN; q++) {
                float va = da[pa], vb = db[pb];
                if (va <= vb) { od[q] = va; oi[q] = ia[pa]; pa++; }
                else          { od[q] = vb; oi[q] = ib[pb]; pb++; }
            }
            #pragma unroll
            for (int q = 0; q < KNN; q++) { da[q] = od[q]; ia[q] = oi[q]; }
        }
        __syncthreads();
    }
    if (tid == 0) {
        float w[KNN], sum = 0.0f;
        float dmin = sd[0];
        #pragma unroll
        for (int q = 0; q < KNN; q++) { w[q] = expf(dmin - sd[q]); sum += w[q]; }
        float inv = 1.0f / sum;
        #pragma unroll
        for (int q = 0; q < KNN; q++) {
            Ew[i*KNN + q] = w[q] * inv;
            Idx[i*KNN + q] = si[q];
        }
    }
}

// ---------------- SGEMM 64x64x16, 256 threads, 4x4 per thread ----------------
// C = [ACC? C :] + SIGN*(A@W) [+ bias] ; ACT -> gelu ; RES -> + Res
template<int ACT, int ACC, int SIGN, int RES>
__global__ __launch_bounds__(256) void gemm64(const float* __restrict__ A,
                                              const float* __restrict__ W,
                                              const float* __restrict__ bias,
                                              const float* __restrict__ Res,
                                              float* __restrict__ C,
                                              int M, int N, int K) {
    __shared__ float As[16][68];
    __shared__ float Bs[16][68];
    int bm = blockIdx.y * 64, bn = blockIdx.x * 64;
    int tid = threadIdx.x;
    int ty = tid >> 4, tx = tid & 15;   // 16x16 threads, 4x4 each
    float acc[4][4];
    #pragma unroll
    for (int i = 0; i < 4; i++)
        #pragma unroll
        for (int j = 0; j < 4; j++) acc[i][j] = 0.0f;

    int am = tid >> 2, ac4 = (tid & 3) * 4;     // A: 64 rows x 16 k
    int wk = tid >> 4, wn4 = (tid & 15) * 4;    // W: 16 rows x 64 n

    for (int k0 = 0; k0 < K; k0 += 16) {
        float4 va = *(const float4*)&A[(size_t)(bm + am)*K + k0 + ac4];
        As[ac4+0][am] = va.x; As[ac4+1][am] = va.y; As[ac4+2][am] = va.z; As[ac4+3][am] = va.w;
        float4 vb = *(const float4*)&W[(size_t)(k0 + wk)*N + bn + wn4];
        *(float4*)&Bs[wk][wn4] = vb;
        __syncthreads();
        #pragma unroll
        for (int k = 0; k < 16; k++) {
            float4 a = *(const float4*)&As[k][ty*4];
            float4 b = *(const float4*)&Bs[k][tx*4];
            float ar[4] = {a.x, a.y, a.z, a.w};
            float br[4] = {b.x, b.y, b.z, b.w};
            #pragma unroll
            for (int i = 0; i < 4; i++)
                #pragma unroll
                for (int j = 0; j < 4; j++) acc[i][j] = fmaf(ar[i], br[j], acc[i][j]);
        }
        __syncthreads();
    }
    #pragma unroll
    for (int i = 0; i < 4; i++) {
        int row = bm + ty*4 + i;
        #pragma unroll
        for (int j = 0; j < 4; j++) {
            int col = bn + tx*4 + j;
            size_t o = (size_t)row*N + col;
            float v = (SIGN > 0) ? acc[i][j] : -acc[i][j];
            if (bias) v += bias[col];
            if (ACC)  v += C[o];
            if (ACT)  v = gelu_exact(v);
            if (RES)  v += Res[o];
            C[o] = v;
        }
    }
}

// ---------------- fused edge kernel: AggH[i] = sum_k ew*gelu(Pp[src]+Qq[i]) ----------------
__global__ __launch_bounds__(256) void edge_agg_kernel(const float* __restrict__ Pp,
                                                       const float* __restrict__ Qq,
                                                       const int* __restrict__ Idx,
                                                       const float* __restrict__ Ew,
                                                       float* __restrict__ AggH) {
    int i = blockIdx.x;
    int t = threadIdx.x; // 256
    __shared__ int   ssrc[KNN];
    __shared__ float sw[KNN];
    if (t < KNN) { ssrc[t] = Idx[i*KNN + t]; sw[t] = Ew[i*KNN + t]; }
    __syncthreads();
    float q = Qq[i*HH + t];
    float acc = 0.0f;
    #pragma unroll
    for (int k = 0; k < KNN; k++) {
        float p = Pp[(size_t)ssrc[k]*HH + t];
        acc = fmaf(sw[k], gelu_exact(p + q), acc);
    }
    AggH[i*HH + t] = acc;
}

// ---------------- concat [s, agg] ----------------
__global__ void cat_kernel(const float* __restrict__ S, const float* __restrict__ Agg,
                           float* __restrict__ Cat) {
    int idx = blockIdx.x * blockDim.x + threadIdx.x; // B*512
    int i = idx >> 9;
    int c = idx & 511;
    Cat[idx] = (c < 256) ? S[i*HH + c] : Agg[i*HH + (c-256)];
}

// ---------------- center categorical blocks in-place ----------------
__global__ void center_kernel(float* __restrict__ Out) {
    int i = blockIdx.x;
    int t = threadIdx.x; // 48
    __shared__ float sv[48];
    float v = Out[i*DD + 64 + t];
    sv[t] = v;
    __syncthreads();
    int g = (t >> 4) << 4;
    float m = 0.0f;
    #pragma unroll
    for (int q = 0; q < 16; q++) m += sv[g + q];
    m *= (1.0f/16.0f);
    Out[i*DD + 64 + t] = v - m;
}

// ---------------- launcher ----------------
extern "C" void kernel_launch(void* const* d_in, const int* in_sizes, int n_in,
                              void* d_out, int out_size) {
    const float* x_c   = (const float*)d_in[0];
    const float* x_d0  = (const float*)d_in[1];
    const float* x_d1  = (const float*)d_in[2];
    const float* x_d2  = (const float*)d_in[3];
    const float* x_o   = (const float*)d_in[4];
    const float* t_emb = (const float*)d_in[5];
    const float* W_in  = (const float*)d_in[6];
    const float* b_in  = (const float*)d_in[7];
    const float* Wm1   = (const float*)d_in[8];
    const float* bm1   = (const float*)d_in[9];
    const float* Wm2   = (const float*)d_in[10];
    const float* bm2   = (const float*)d_in[11];
    const float* Wu1   = (const float*)d_in[12];
    const float* bu1   = (const float*)d_in[13];
    const float* Wu2   = (const float*)d_in[14];
    const float* bu2   = (const float*)d_in[15];
    const float* W_out = (const float*)d_in[16];
    const float* b_out = (const float*)d_in[17];
    float* out = (float*)d_out;

    float *x, *dist, *ew, *s, *pp, *qq, *aggh, *agg, *cat, *u1;
    int* idx;
    cudaGetSymbolAddress((void**)&x,    g_x);
    cudaGetSymbolAddress((void**)&dist, g_dist);
    cudaGetSymbolAddress((void**)&idx,  g_idx);
    cudaGetSymbolAddress((void**)&ew,   g_ew);
    cudaGetSymbolAddress((void**)&s,    g_s);
    cudaGetSymbolAddress((void**)&pp,   g_pp);
    cudaGetSymbolAddress((void**)&qq,   g_qq);
    cudaGetSymbolAddress((void**)&aggh, g_aggh);
    cudaGetSymbolAddress((void**)&agg,  g_agg);
    cudaGetSymbolAddress((void**)&cat,  g_cat);
    cudaGetSymbolAddress((void**)&u1,   g_u1);

    build_x_kernel<<<BN_, 128>>>(x_c, x_d0, x_d1, x_d2, x_o, x);
    cdist_kernel<<<dim3(BN_/128, BN_/128), 256>>>(x, dist);
    topk_kernel<<<BN_, 256>>>(dist, idx, ew);

    dim3 gB(HH/64, BN_/64);   // N=256 grids
    dim3 gO(DD/64, BN_/64);   // N=128 grid (output)

    // s = x @ W_in + b_in
    gemm64<0,0,1,0><<<gB, 256>>>(x, W_in, b_in, nullptr, s, BN_, HH, DD);

    // Wm1 layout (per layer): rows [0:256)=W1a (s[src]), [256:512)=W1b (s[dst]),
    // [512:640)=W1c (x[src]-x[dst]), [640:704)=W1d (t_emb[dst])
    for (int l = 0; l < NL; l++) {
        const float* wm1 = Wm1 + (size_t)l * 704 * HH;
        const float* w1a = wm1;
        const float* w1b = wm1 + (size_t)256 * HH;
        const float* w1c = wm1 + (size_t)512 * HH;
        const float* w1d = wm1 + (size_t)640 * HH;
        const float* wm2 = Wm2 + (size_t)l * HH * HH;
        const float* wu1 = Wu1 + (size_t)l * 2*HH * HH;
        const float* wu2 = Wu2 + (size_t)l * HH * HH;

        // Pp = s@W1a + x@W1c
        gemm64<0,0,1,0><<<gB, 256>>>(s, w1a, nullptr, nullptr, pp, BN_, HH, HH);
        gemm64<0,1,1,0><<<gB, 256>>>(x, w1c, nullptr, nullptr, pp, BN_, HH, DD);
        // Qq = s@W1b + bm1 + t@W1d - x@W1c
        gemm64<0,0,1,0><<<gB, 256>>>(s, w1b, bm1 + l*HH, nullptr, qq, BN_, HH, HH);
        gemm64<0,1,1,0><<<gB, 256>>>(t_emb, w1d, nullptr, nullptr, qq, BN_, HH, TT);
        gemm64<0,1,-1,0><<<gB, 256>>>(x, w1c, nullptr, nullptr, qq, BN_, HH, DD);
        // AggH[i] = sum_k ew * gelu(Pp[src] + Qq[i])
        edge_agg_kernel<<<BN_, 256>>>(pp, qq, idx, ew, aggh);
        // agg = AggH @ Wm2 + bm2   (softmax weights sum to 1)
        gemm64<0,0,1,0><<<gB, 256>>>(aggh, wm2, bm2 + l*HH, nullptr, agg, BN_, HH, HH);
        // cat = [s, agg]
        cat_kernel<<<BN_*2*HH/256, 256>>>(s, agg, cat);
        // u1 = gelu(cat @ Wu1 + bu1)
        gemm64<1,0,1,0><<<gB, 256>>>(cat, wu1, bu1 + l*HH, nullptr, u1, BN_, HH, 2*HH);
        // s = s + (u1 @ Wu2 + bu2)
        gemm64<0,0,1,1><<<gB, 256>>>(u1, wu2, bu2 + l*HH, s, s, BN_, HH, HH);
    }

    // out = s @ W_out + b_out, then center categorical blocks
    gemm64<0,0,1,0><<<gO, 256>>>(s, W_out, b_out, nullptr, out, BN_, DD, HH);
    center_kernel<<<BN_, 48>>>(out);
}

// round 3
// speedup vs baseline: 3.7079x; 1.2220x over previous
#include <cuda_runtime.h>
#include <cuda_bf16.h>
#include <math.h>

#define BN_ 4096      // batch
#define DD  128       // feature dim
#define HH  256       // hidden
#define TT  64        // time emb
#define KNN 10
#define NL  2
#define ZW  448       // Z row width: [s(256) | x(128) | t(64)]

typedef unsigned long long u64;
typedef unsigned int u32;

// ---------------- static scratch ----------------
__device__ __align__(128) float g_z[BN_*ZW];             // [s | x | t]
__device__ __align__(128) float g_dist[(size_t)BN_*BN_]; // 64 MB
__device__ __align__(128) int   g_idx[BN_*KNN];
__device__ __align__(128) float g_ew[BN_*KNN];
__device__ __align__(128) float g_pp[BN_*HH];
__device__ __align__(128) float g_qq[BN_*HH];
__device__ __align__(128) float g_aggh[BN_*HH];
__device__ __align__(128) float g_cat[BN_*2*HH];
__device__ __align__(128) float g_u1[BN_*HH];
__device__ __align__(128) float g_wp[NL*384*HH];         // [W1a; W1c]
__device__ __align__(128) float g_wq[NL*448*HH];         // [W1b; -W1c; W1d]

__device__ __forceinline__ float gelu_exact(float x) {
    return 0.5f * x * (1.0f + erff(x * 0.70710678118654752440f));
}

__device__ __forceinline__ u64 pack_f2(float x, float y) {
    u64 r; asm("mov.b64 %0, {%1, %2};" : "=l"(r) : "f"(x), "f"(y)); return r;
}
__device__ __forceinline__ float2 unpack_f2(u64 v) {
    float2 f; asm("mov.b64 {%0, %1}, %2;" : "=f"(f.x), "=f"(f.y) : "l"(v)); return f;
}
// acc += |a + nb|  elementwise on packed f32x2 (nb is pre-negated b)
__device__ __forceinline__ void l1_acc(u64& acc, u64 a, u64 nb) {
    u64 d;
    asm("add.rn.f32x2 %0, %1, %2;" : "=l"(d) : "l"(a), "l"(nb));
    u32 lo = (u32)d & 0x7fffffffu;
    u32 hi = (u32)(d >> 32) & 0x7fffffffu;
    u64 m = ((u64)hi << 32) | (u64)lo;
    asm("add.rn.f32x2 %0, %0, %1;" : "+l"(acc) : "l"(m));
}

// ---------------- build Z = [s(later) | x | t] ----------------
__global__ void build_z_kernel(const float* __restrict__ xc, const float* __restrict__ d0,
                               const float* __restrict__ d1, const float* __restrict__ d2,
                               const float* __restrict__ xo, const float* __restrict__ te,
                               float* __restrict__ Z) {
    int i = blockIdx.x;
    int t = threadIdx.x; // 192
    float v; int c;
    if (t < 128) {
        if (t < 64)       v = xc[i*64 + t];
        else if (t < 80)  v = d0[i*16 + (t-64)];
        else if (t < 96)  v = d1[i*16 + (t-80)];
        else if (t < 112) v = d2[i*16 + (t-96)];
        else              v = xo[i*16 + (t-112)];
        c = 256 + t;
    } else {
        v = te[i*TT + (t-128)];
        c = 384 + (t-128);
    }
    Z[(size_t)i*ZW + c] = v;
}

// ---------------- rearranged message weights ----------------
__global__ void rearrange_w_kernel(const float* __restrict__ Wm1,
                                   float* __restrict__ Wp, float* __restrict__ Wq) {
    int idx = blockIdx.x * 256 + threadIdx.x; // NL*(384+448)*256
    int l = idx / (832*HH);
    int r2 = idx - l*(832*HH);
    int r = r2 / HH, c = r2 - (r2/HH)*HH;
    const float* w = Wm1 + (size_t)l*704*HH;
    if (r < 384) {
        int sr = (r < 256) ? r : (512 + (r - 256));
        Wp[(size_t)l*384*HH + r*HH + c] = w[sr*HH + c];
    } else {
        int rq = r - 384;
        float sgn = 1.0f; int sr;
        if (rq < 256)      sr = 256 + rq;
        else if (rq < 384) { sr = 512 + (rq - 256); sgn = -1.0f; }
        else               sr = 640 + (rq - 384);
        Wq[(size_t)l*448*HH + rq*HH + c] = sgn * w[sr*HH + c];
    }
}

// ---------------- symmetric L1 cdist, 128x128 tiles, packed f32x2 ----------------
// X = Z + 256, lda = ZW. Only tiles bn>=bm computed; both tiles stored.
__global__ __launch_bounds__(512) void cdist_kernel(const float* __restrict__ X,
                                                    float* __restrict__ Dist) {
    __shared__ u64 As2[8][128];
    __shared__ u64 Bs2[8][128];
    // map linear block -> upper-triangular tile pair
    int r = 0, rem = blockIdx.x;
    while (rem >= 32 - r) { rem -= 32 - r; r++; }
    int bm = r * 128, bn = (r + rem) * 128;

    int tid = threadIdx.x;
    int ty = tid >> 5;        // 0..15 -> 8 rows each
    int tx = tid & 31;        // 0..31 -> 4 cols each
    u64 acc2[8][4];
    #pragma unroll
    for (int i = 0; i < 8; i++)
        #pragma unroll
        for (int j = 0; j < 4; j++) acc2[i][j] = 0ull;

    int lrow = tid >> 2;          // 0..127
    int lq   = (tid & 3) * 4;     // 0,4,8,12

    for (int k0 = 0; k0 < DD; k0 += 16) {
        float4 va = *(const float4*)&X[(size_t)(bm + lrow)*ZW + k0 + lq];
        As2[(lq>>1)+0][lrow] = pack_f2(va.x, va.y);
        As2[(lq>>1)+1][lrow] = pack_f2(va.z, va.w);
        float4 vb = *(const float4*)&X[(size_t)(bn + lrow)*ZW + k0 + lq];
        Bs2[(lq>>1)+0][lrow] = pack_f2(-vb.x, -vb.y);
        Bs2[(lq>>1)+1][lrow] = pack_f2(-vb.z, -vb.w);
        __syncthreads();
        #pragma unroll
        for (int kk = 0; kk < 8; kk++) {
            u64 a2[8], b2[4];
            #pragma unroll
            for (int i = 0; i < 8; i++) a2[i] = As2[kk][ty*8 + i];
            #pragma unroll
            for (int j = 0; j < 4; j++) b2[j] = Bs2[kk][tx*4 + j];
            #pragma unroll
            for (int i = 0; i < 8; i++)
                #pragma unroll
                for (int j = 0; j < 4; j++) l1_acc(acc2[i][j], a2[i], b2[j]);
        }
        __syncthreads();
    }
    float res[8][4];
    #pragma unroll
    for (int i = 0; i < 8; i++)
        #pragma unroll
        for (int j = 0; j < 4; j++) {
            float2 f = unpack_f2(acc2[i][j]);
            res[i][j] = f.x + f.y;
        }
    // normal tile
    #pragma unroll
    for (int i = 0; i < 8; i++) {
        float4 v = make_float4(res[i][0], res[i][1], res[i][2], res[i][3]);
        *(float4*)&Dist[(size_t)(bm + ty*8 + i)*BN_ + bn + tx*4] = v;
    }
    // transposed tile
    if (bm != bn) {
        #pragma unroll
        for (int j = 0; j < 4; j++) {
            float4 v0 = make_float4(res[0][j], res[1][j], res[2][j], res[3][j]);
            float4 v1 = make_float4(res[4][j], res[5][j], res[6][j], res[7][j]);
            size_t o = (size_t)(bn + tx*4 + j)*BN_ + bm + ty*8;
            *(float4*)&Dist[o]     = v0;
            *(float4*)&Dist[o + 4] = v1;
        }
    }
}

// ---------------- top-K + softmax edge weights ----------------
__global__ __launch_bounds__(256) void topk_kernel(const float* __restrict__ Dist,
                                                   int* __restrict__ Idx,
                                                   float* __restrict__ Ew) {
    int i = blockIdx.x;
    int tid = threadIdx.x;
    float best[KNN]; int bidx[KNN];
    #pragma unroll
    for (int q = 0; q < KNN; q++) { best[q] = 3.0e38f; bidx[q] = -1; }
    const float4* row = (const float4*)(Dist + (size_t)i * BN_);
    for (int jv = tid; jv < BN_/4; jv += 256) {
        float4 d4 = row[jv];
        float dv[4] = {d4.x, d4.y, d4.z, d4.w};
        #pragma unroll
        for (int q4 = 0; q4 < 4; q4++) {
            int j = jv*4 + q4;
            float d = dv[q4];
            if (j == i) continue;
            if (d < best[KNN-1]) {
                float dd = d; int ii = j;
                #pragma unroll
                for (int q = 0; q < KNN; q++) {
                    if (dd < best[q]) {
                        float tb = best[q]; int ti = bidx[q];
                        best[q] = dd; bidx[q] = ii;
                        dd = tb; ii = ti;
                    }
                }
            }
        }
    }
    __shared__ float sd[256*KNN];
    __shared__ int   si[256*KNN];
    #pragma unroll
    for (int q = 0; q < KNN; q++) { sd[tid*KNN+q] = best[q]; si[tid*KNN+q] = bidx[q]; }
    __syncthreads();
    for (int stride = 128; stride >= 1; stride >>= 1) {
        if (tid < stride) {
            float* da = &sd[tid*KNN];          int* ia = &si[tid*KNN];
            float* db = &sd[(tid+stride)*KNN]; int* ib = &si[(tid+stride)*KNN];
            float od[KNN]; int oi[KNN];
            int pa = 0, pb = 0;
            #pragma unroll
            for (int q = 0; q < KNN; q++) {
                float va = da[pa], vb = db[pb];
                if (va <= vb) { od[q] = va; oi[q] = ia[pa]; pa++; }
                else          { od[q] = vb; oi[q] = ib[pb]; pb++; }
            }
            #pragma unroll
            for (int q = 0; q < KNN; q++) { da[q] = od[q]; ia[q] = oi[q]; }
        }
        __syncthreads();
    }
    if (tid == 0) {
        float w[KNN], sum = 0.0f;
        float dmin = sd[0];
        #pragma unroll
        for (int q = 0; q < KNN; q++) { w[q] = expf(dmin - sd[q]); sum += w[q]; }
        float inv = 1.0f / sum;
        #pragma unroll
        for (int q = 0; q < KNN; q++) {
            Ew[i*KNN + q] = w[q] * inv;
            Idx[i*KNN + q] = si[q];
        }
    }
}

// ---------------- SGEMM core: 64x64x16, 256 threads, 4x4 per thread ----------------
template<int ACT, int ACC>
__device__ __forceinline__ void gemm_core(const float* __restrict__ A, int lda,
                                          const float* __restrict__ W, int ldw,
                                          const float* __restrict__ bias,
                                          float* __restrict__ C, int ldc,
                                          int K, int bm, int bn) {
    __shared__ float As[16][68];
    __shared__ float Bs[16][68];
    int tid = threadIdx.x;
    int ty = tid >> 4, tx = tid & 15;
    float acc[4][4];
    #pragma unroll
    for (int i = 0; i < 4; i++)
        #pragma unroll
        for (int j = 0; j < 4; j++) acc[i][j] = 0.0f;

    int am = tid >> 2, ac4 = (tid & 3) * 4;
    int wk = tid >> 4, wn4 = (tid & 15) * 4;

    for (int k0 = 0; k0 < K; k0 += 16) {
        float4 va = *(const float4*)&A[(size_t)(bm + am)*lda + k0 + ac4];
        As[ac4+0][am] = va.x; As[ac4+1][am] = va.y; As[ac4+2][am] = va.z; As[ac4+3][am] = va.w;
        float4 vb = *(const float4*)&W[(size_t)(k0 + wk)*ldw + bn + wn4];
        *(float4*)&Bs[wk][wn4] = vb;
        __syncthreads();
        #pragma unroll
        for (int k = 0; k < 16; k++) {
            float4 a = *(const float4*)&As[k][ty*4];
            float4 b = *(const float4*)&Bs[k][tx*4];
            float ar[4] = {a.x, a.y, a.z, a.w};
            float br[4] = {b.x, b.y, b.z, b.w};
            #pragma unroll
            for (int i = 0; i < 4; i++)
                #pragma unroll
                for (int j = 0; j < 4; j++) acc[i][j] = fmaf(ar[i], br[j], acc[i][j]);
        }
        __syncthreads();
    }
    #pragma unroll
    for (int i = 0; i < 4; i++) {
        int row = bm + ty*4 + i;
        #pragma unroll
        for (int j = 0; j < 4; j++) {
            int col = bn + tx*4 + j;
            size_t o = (size_t)row*ldc + col;
            float v = acc[i][j];
            if (bias) v += bias[col];
            if (ACC)  v += C[o];
            if (ACT)  v = gelu_exact(v);
            C[o] = v;
        }
    }
}

template<int ACT, int ACC>
__global__ __launch_bounds__(256) void gemm64(const float* __restrict__ A, int lda,
                                              const float* __restrict__ W, int ldw,
                                              const float* __restrict__ bias,
                                              float* __restrict__ C, int ldc, int K) {
    gemm_core<ACT,ACC>(A, lda, W, ldw, bias, C, ldc, K, blockIdx.y*64, blockIdx.x*64);
}

// z-batched Pp/Qq GEMMs: z=0 -> Pp = Z[:, :384] @ Wp ; z=1 -> Qq = Z @ Wq + bm1
__global__ __launch_bounds__(256) void pq_gemm(const float* __restrict__ Z,
                                               const float* __restrict__ Wp,
                                               const float* __restrict__ Wq,
                                               const float* __restrict__ bm1l,
                                               float* __restrict__ Pp,
                                               float* __restrict__ Qq) {
    if (blockIdx.z == 0)
        gemm_core<0,0>(Z, ZW, Wp, HH, nullptr, Pp, HH, 384, blockIdx.y*64, blockIdx.x*64);
    else
        gemm_core<0,0>(Z, ZW, Wq, HH, bm1l,   Qq, HH, 448, blockIdx.y*64, blockIdx.x*64);
}

// ---------------- fused edge kernel + cat-left copy ----------------
// AggH[i] = sum_k ew*gelu(Pp[src]+Qq[i]) ; Cat[i][0:256] = s[i]
__global__ __launch_bounds__(256) void edge_agg_kernel(const float* __restrict__ Pp,
                                                       const float* __restrict__ Qq,
                                                       const float* __restrict__ Z,
                                                       const int* __restrict__ Idx,
                                                       const float* __restrict__ Ew,
                                                       float* __restrict__ AggH,
                                                       float* __restrict__ Cat) {
    int i = blockIdx.x;
    int t = threadIdx.x; // 256
    __shared__ int   ssrc[KNN];
    __shared__ float sw[KNN];
    if (t < KNN) { ssrc[t] = Idx[i*KNN + t]; sw[t] = Ew[i*KNN + t]; }
    __syncthreads();
    float q = Qq[i*HH + t];
    float acc = 0.0f;
    #pragma unroll
    for (int k = 0; k < KNN; k++) {
        float p = Pp[(size_t)ssrc[k]*HH + t];
        acc = fmaf(sw[k], gelu_exact(p + q), acc);
    }
    AggH[i*HH + t] = acc;
    Cat[(size_t)i*2*HH + t] = Z[(size_t)i*ZW + t];
}

// ---------------- center categorical blocks in-place ----------------
__global__ void center_kernel(float* __restrict__ Out) {
    int i = blockIdx.x;
    int t = threadIdx.x; // 48
    __shared__ float sv[48];
    float v = Out[i*DD + 64 + t];
    sv[t] = v;
    __syncthreads();
    int g = (t >> 4) << 4;
    float m = 0.0f;
    #pragma unroll
    for (int q = 0; q < 16; q++) m += sv[g + q];
    m *= (1.0f/16.0f);
    Out[i*DD + 64 + t] = v - m;
}

// ---------------- launcher ----------------
extern "C" void kernel_launch(void* const* d_in, const int* in_sizes, int n_in,
                              void* d_out, int out_size) {
    const float* x_c   = (const float*)d_in[0];
    const float* x_d0  = (const float*)d_in[1];
    const float* x_d1  = (const float*)d_in[2];
    const float* x_d2  = (const float*)d_in[3];
    const float* x_o   = (const float*)d_in[4];
    const float* t_emb = (const float*)d_in[5];
    const float* W_in  = (const float*)d_in[6];
    const float* b_in  = (const float*)d_in[7];
    const float* Wm1   = (const float*)d_in[8];
    const float* bm1   = (const float*)d_in[9];
    const float* Wm2   = (const float*)d_in[10];
    const float* bm2   = (const float*)d_in[11];
    const float* Wu1   = (const float*)d_in[12];
    const float* bu1   = (const float*)d_in[13];
    const float* Wu2   = (const float*)d_in[14];
    const float* bu2   = (const float*)d_in[15];
    const float* W_out = (const float*)d_in[16];
    const float* b_out = (const float*)d_in[17];
    float* out = (float*)d_out;

    float *z, *dist, *ew, *pp, *qq, *aggh, *cat, *u1, *wp, *wq;
    int* idx;
    cudaGetSymbolAddress((void**)&z,    g_z);
    cudaGetSymbolAddress((void**)&dist, g_dist);
    cudaGetSymbolAddress((void**)&idx,  g_idx);
    cudaGetSymbolAddress((void**)&ew,   g_ew);
    cudaGetSymbolAddress((void**)&pp,   g_pp);
    cudaGetSymbolAddress((void**)&qq,   g_qq);
    cudaGetSymbolAddress((void**)&aggh, g_aggh);
    cudaGetSymbolAddress((void**)&cat,  g_cat);
    cudaGetSymbolAddress((void**)&u1,   g_u1);
    cudaGetSymbolAddress((void**)&wp,   g_wp);
    cudaGetSymbolAddress((void**)&wq,   g_wq);

    build_z_kernel<<<BN_, 192>>>(x_c, x_d0, x_d1, x_d2, x_o, t_emb, z);
    rearrange_w_kernel<<<(NL*832*HH)/256, 256>>>(Wm1, wp, wq);
    cdist_kernel<<<528, 512>>>(z + 256, dist);
    topk_kernel<<<BN_, 256>>>(dist, idx, ew);

    dim3 gB(HH/64, BN_/64);
    dim3 gPQ(HH/64, BN_/64, 2);
    dim3 gO(DD/64, BN_/64);

    // s = x @ W_in + b_in  -> Z[:, 0:256]
    gemm64<0,0><<<gB, 256>>>(z + 256, ZW, W_in, HH, b_in, z, ZW, DD);

    for (int l = 0; l < NL; l++) {
        const float* wpl = wp + (size_t)l * 384 * HH;
        const float* wql = wq + (size_t)l * 448 * HH;
        const float* wm2 = Wm2 + (size_t)l * HH * HH;
        const float* wu1 = Wu1 + (size_t)l * 2*HH * HH;
        const float* wu2 = Wu2 + (size_t)l * HH * HH;

        // Pp = [s|x] @ Wp ; Qq = [s|x|t] @ Wq + bm1
        pq_gemm<<<gPQ, 256>>>(z, wpl, wql, bm1 + l*HH, pp, qq);
        // AggH[i] = sum_k ew*gelu(Pp[src]+Qq[i]) ; Cat left = s
        edge_agg_kernel<<<BN_, 256>>>(pp, qq, z, idx, ew, aggh, cat);
        // Cat right = AggH @ Wm2 + bm2
        gemm64<0,0><<<gB, 256>>>(aggh, HH, wm2, HH, bm2 + l*HH, cat + HH, 2*HH, HH);
        // u1 = gelu(cat @ Wu1 + bu1)
        gemm64<1,0><<<gB, 256>>>(cat, 2*HH, wu1, HH, bu1 + l*HH, u1, HH, 2*HH);
        // s += u1 @ Wu2 + bu2   (in place in Z)
        gemm64<0,1><<<gB, 256>>>(u1, HH, wu2, HH, bu2 + l*HH, z, ZW, HH);
    }

    // out = s @ W_out + b_out, then center categorical blocks
    gemm64<0,0><<<gO, 256>>>(z, ZW, W_out, DD, b_out, out, DD, HH);
    center_kernel<<<BN_, 48>>>(out);
}

// round 4
// speedup vs baseline: 3.9082x; 1.0540x over previous
#include <cuda_runtime.h>
#include <cuda_bf16.h>
#include <math.h>

#define BN_ 4096      // batch
#define DD  128       // feature dim
#define HH  256       // hidden
#define TT  64        // time emb
#define KNN 10
#define NL  2
#define ZW  448       // Z row width: [s(256) | x(128) | t(64)]

typedef unsigned long long u64;
typedef unsigned int u32;

// ---------------- static scratch ----------------
__device__ __align__(128) float g_z[BN_*ZW];             // [s | x | t]
__device__ __align__(128) float g_dist[(size_t)BN_*BN_]; // 64 MB
__device__ __align__(128) int   g_idx[BN_*KNN];
__device__ __align__(128) float g_ew[BN_*KNN];
__device__ __align__(128) float g_pp[BN_*HH];
__device__ __align__(128) float g_qq[BN_*HH];
__device__ __align__(128) float g_aggh[BN_*HH];
__device__ __align__(128) float g_cat[BN_*2*HH];
__device__ __align__(128) float g_u1[BN_*HH];
__device__ __align__(128) float g_wp[NL*384*HH];         // [W1a; W1c]
__device__ __align__(128) float g_wq[NL*448*HH];         // [W1b; -W1c; W1d]

__device__ __forceinline__ float gelu_exact(float x) {
    return 0.5f * x * (1.0f + erff(x * 0.70710678118654752440f));
}

__device__ __forceinline__ u64 pack_f2(float x, float y) {
    u64 r; asm("mov.b64 %0, {%1, %2};" : "=l"(r) : "f"(x), "f"(y)); return r;
}
__device__ __forceinline__ float2 unpack_f2(u64 v) {
    float2 f; asm("mov.b64 {%0, %1}, %2;" : "=f"(f.x), "=f"(f.y) : "l"(v)); return f;
}
// acc += |a + nb|  elementwise on packed f32x2 (nb is pre-negated b)
__device__ __forceinline__ void l1_acc(u64& acc, u64 a, u64 nb) {
    u64 d;
    asm("add.rn.f32x2 %0, %1, %2;" : "=l"(d) : "l"(a), "l"(nb));
    u32 lo = (u32)d & 0x7fffffffu;
    u32 hi = (u32)(d >> 32) & 0x7fffffffu;
    u64 m = ((u64)hi << 32) | (u64)lo;
    asm("add.rn.f32x2 %0, %0, %1;" : "+l"(acc) : "l"(m));
}

// ---------------- tf32 helpers ----------------
__device__ __forceinline__ void split_tf32(float x, u32& hi, u32& lo) {
    asm("cvt.rna.tf32.f32 %0, %1;" : "=r"(hi) : "f"(x));
    float r = x - __uint_as_float(hi);
    asm("cvt.rna.tf32.f32 %0, %1;" : "=r"(lo) : "f"(r));
}
__device__ __forceinline__ void mma8(float* c, const u32* a, const u32* b) {
    asm volatile("mma.sync.aligned.m16n8k8.row.col.f32.tf32.tf32.f32 "
                 "{%0,%1,%2,%3}, {%4,%5,%6,%7}, {%8,%9}, {%0,%1,%2,%3};"
                 : "+f"(c[0]), "+f"(c[1]), "+f"(c[2]), "+f"(c[3])
                 : "r"(a[0]), "r"(a[1]), "r"(a[2]), "r"(a[3]),
                   "r"(b[0]), "r"(b[1]));
}

// ---------------- build Z = [s(later) | x | t] ----------------
__global__ void build_z_kernel(const float* __restrict__ xc, const float* __restrict__ d0,
                               const float* __restrict__ d1, const float* __restrict__ d2,
                               const float* __restrict__ xo, const float* __restrict__ te,
                               float* __restrict__ Z) {
    int i = blockIdx.x;
    int t = threadIdx.x; // 192
    float v; int c;
    if (t < 128) {
        if (t < 64)       v = xc[i*64 + t];
        else if (t < 80)  v = d0[i*16 + (t-64)];
        else if (t < 96)  v = d1[i*16 + (t-80)];
        else if (t < 112) v = d2[i*16 + (t-96)];
        else              v = xo[i*16 + (t-112)];
        c = 256 + t;
    } else {
        v = te[i*TT + (t-128)];
        c = 384 + (t-128);
    }
    Z[(size_t)i*ZW + c] = v;
}

// ---------------- rearranged message weights ----------------
__global__ void rearrange_w_kernel(const float* __restrict__ Wm1,
                                   float* __restrict__ Wp, float* __restrict__ Wq) {
    int idx = blockIdx.x * 256 + threadIdx.x; // NL*(384+448)*256
    int l = idx / (832*HH);
    int r2 = idx - l*(832*HH);
    int r = r2 / HH, c = r2 - (r2/HH)*HH;
    const float* w = Wm1 + (size_t)l*704*HH;
    if (r < 384) {
        int sr = (r < 256) ? r : (512 + (r - 256));
        Wp[(size_t)l*384*HH + r*HH + c] = w[sr*HH + c];
    } else {
        int rq = r - 384;
        float sgn = 1.0f; int sr;
        if (rq < 256)      sr = 256 + rq;
        else if (rq < 384) { sr = 512 + (rq - 256); sgn = -1.0f; }
        else               sr = 640 + (rq - 384);
        Wq[(size_t)l*448*HH + rq*HH + c] = sgn * w[sr*HH + c];
    }
}

// ---------------- symmetric L1 cdist, 128x128 tiles, packed f32x2 ----------------
__global__ __launch_bounds__(512) void cdist_kernel(const float* __restrict__ X,
                                                    float* __restrict__ Dist) {
    __shared__ u64 As2[8][128];
    __shared__ u64 Bs2[8][128];
    int r = 0, rem = blockIdx.x;
    while (rem >= 32 - r) { rem -= 32 - r; r++; }
    int bm = r * 128, bn = (r + rem) * 128;

    int tid = threadIdx.x;
    int ty = tid >> 5;
    int tx = tid & 31;
    u64 acc2[8][4];
    #pragma unroll
    for (int i = 0; i < 8; i++)
        #pragma unroll
        for (int j = 0; j < 4; j++) acc2[i][j] = 0ull;

    int lrow = tid >> 2;
    int lq   = (tid & 3) * 4;

    for (int k0 = 0; k0 < DD; k0 += 16) {
        float4 va = *(const float4*)&X[(size_t)(bm + lrow)*ZW + k0 + lq];
        As2[(lq>>1)+0][lrow] = pack_f2(va.x, va.y);
        As2[(lq>>1)+1][lrow] = pack_f2(va.z, va.w);
        float4 vb = *(const float4*)&X[(size_t)(bn + lrow)*ZW + k0 + lq];
        Bs2[(lq>>1)+0][lrow] = pack_f2(-vb.x, -vb.y);
        Bs2[(lq>>1)+1][lrow] = pack_f2(-vb.z, -vb.w);
        __syncthreads();
        #pragma unroll
        for (int kk = 0; kk < 8; kk++) {
            u64 a2[8], b2[4];
            #pragma unroll
            for (int i = 0; i < 8; i++) a2[i] = As2[kk][ty*8 + i];
            #pragma unroll
            for (int j = 0; j < 4; j++) b2[j] = Bs2[kk][tx*4 + j];
            #pragma unroll
            for (int i = 0; i < 8; i++)
                #pragma unroll
                for (int j = 0; j < 4; j++) l1_acc(acc2[i][j], a2[i], b2[j]);
        }
        __syncthreads();
    }
    float res[8][4];
    #pragma unroll
    for (int i = 0; i < 8; i++)
        #pragma unroll
        for (int j = 0; j < 4; j++) {
            float2 f = unpack_f2(acc2[i][j]);
            res[i][j] = f.x + f.y;
        }
    #pragma unroll
    for (int i = 0; i < 8; i++) {
        float4 v = make_float4(res[i][0], res[i][1], res[i][2], res[i][3]);
        *(float4*)&Dist[(size_t)(bm + ty*8 + i)*BN_ + bn + tx*4] = v;
    }
    if (bm != bn) {
        #pragma unroll
        for (int j = 0; j < 4; j++) {
            float4 v0 = make_float4(res[0][j], res[1][j], res[2][j], res[3][j]);
            float4 v1 = make_float4(res[4][j], res[5][j], res[6][j], res[7][j]);
            size_t o = (size_t)(bn + tx*4 + j)*BN_ + bm + ty*8;
            *(float4*)&Dist[o]     = v0;
            *(float4*)&Dist[o + 4] = v1;
        }
    }
}

// ---------------- top-K with packed u64 keys ----------------
__global__ __launch_bounds__(128) void topk_kernel(const float* __restrict__ Dist,
                                                   int* __restrict__ Idx,
                                                   float* __restrict__ Ew) {
    int i = blockIdx.x;
    int tid = threadIdx.x;
    u64 best[KNN];
    #pragma unroll
    for (int q = 0; q < KNN; q++) best[q] = ~0ull;
    const float4* row = (const float4*)(Dist + (size_t)i * BN_);
    for (int jv = tid; jv < BN_/4; jv += 128) {
        float4 d4 = row[jv];
        float dv[4] = {d4.x, d4.y, d4.z, d4.w};
        #pragma unroll
        for (int q4 = 0; q4 < 4; q4++) {
            int j = jv*4 + q4;
            if (j == i) continue;
            u64 key = ((u64)__float_as_uint(dv[q4]) << 32) | (u32)j;
            if (key < best[KNN-1]) {
                u64 kk = key;
                #pragma unroll
                for (int q = 0; q < KNN; q++) {
                    if (kk < best[q]) { u64 t = best[q]; best[q] = kk; kk = t; }
                }
            }
        }
    }
    __shared__ u64 sk[128*KNN];
    #pragma unroll
    for (int q = 0; q < KNN; q++) sk[tid*KNN+q] = best[q];
    __syncthreads();
    for (int stride = 64; stride >= 1; stride >>= 1) {
        if (tid < stride) {
            u64* da = &sk[tid*KNN];
            u64* db = &sk[(tid+stride)*KNN];
            u64 od[KNN];
            int pa = 0, pb = 0;
            #pragma unroll
            for (int q = 0; q < KNN; q++) {
                u64 va = da[pa], vb = db[pb];
                if (va <= vb) { od[q] = va; pa++; }
                else          { od[q] = vb; pb++; }
            }
            #pragma unroll
            for (int q = 0; q < KNN; q++) da[q] = od[q];
        }
        __syncthreads();
    }
    if (tid == 0) {
        float d[KNN]; int ix[KNN];
        #pragma unroll
        for (int q = 0; q < KNN; q++) {
            d[q]  = __uint_as_float((u32)(sk[q] >> 32));
            ix[q] = (int)(u32)(sk[q] & 0xffffffffu);
        }
        float w[KNN], sum = 0.0f;
        float dmin = d[0];
        #pragma unroll
        for (int q = 0; q < KNN; q++) { w[q] = expf(dmin - d[q]); sum += w[q]; }
        float inv = 1.0f / sum;
        #pragma unroll
        for (int q = 0; q < KNN; q++) {
            Ew[i*KNN + q] = w[q] * inv;
            Idx[i*KNN + q] = ix[q];
        }
    }
}

// ---------------- tf32 tensor-core GEMM, 64x64 tile, 128 thr, split-precision ----------------
template<int ACT, int ACC>
__device__ __forceinline__ void gemm_tc(const float* __restrict__ A, int lda,
                                        const float* __restrict__ W, int ldw,
                                        const float* __restrict__ bias,
                                        float* __restrict__ C, int ldc,
                                        int K, int bm, int bn) {
    __shared__ float As[16][72];
    __shared__ float Bs[16][72];
    int tid = threadIdx.x, lane = tid & 31, wid = tid >> 5;
    int wm = (wid >> 1) * 32, wn = (wid & 1) * 32;
    float c[2][4][4];
    #pragma unroll
    for (int mb = 0; mb < 2; mb++)
        #pragma unroll
        for (int nb = 0; nb < 4; nb++)
            #pragma unroll
            for (int q = 0; q < 4; q++) c[mb][nb][q] = 0.0f;

    int am = tid >> 1, ak = (tid & 1) * 8;
    int wk = tid >> 3, wn8 = (tid & 7) * 8;
    int ar = lane >> 2, ac = lane & 3;
    int bc = lane >> 2, br = lane & 3;

    for (int k0 = 0; k0 < K; k0 += 16) {
        float4 va0 = *(const float4*)&A[(size_t)(bm + am)*lda + k0 + ak];
        float4 va1 = *(const float4*)&A[(size_t)(bm + am)*lda + k0 + ak + 4];
        As[ak+0][am] = va0.x; As[ak+1][am] = va0.y; As[ak+2][am] = va0.z; As[ak+3][am] = va0.w;
        As[ak+4][am] = va1.x; As[ak+5][am] = va1.y; As[ak+6][am] = va1.z; As[ak+7][am] = va1.w;
        float4 vb0 = *(const float4*)&W[(size_t)(k0 + wk)*ldw + bn + wn8];
        float4 vb1 = *(const float4*)&W[(size_t)(k0 + wk)*ldw + bn + wn8 + 4];
        *(float4*)&Bs[wk][wn8]     = vb0;
        *(float4*)&Bs[wk][wn8 + 4] = vb1;
        __syncthreads();
        #pragma unroll
        for (int ks = 0; ks < 16; ks += 8) {
            u32 ahi[2][4], alo[2][4];
            #pragma unroll
            for (int mb = 0; mb < 2; mb++) {
                float x0 = As[ks+ac  ][wm + mb*16 + ar];
                float x1 = As[ks+ac  ][wm + mb*16 + ar + 8];
                float x2 = As[ks+ac+4][wm + mb*16 + ar];
                float x3 = As[ks+ac+4][wm + mb*16 + ar + 8];
                split_tf32(x0, ahi[mb][0], alo[mb][0]);
                split_tf32(x1, ahi[mb][1], alo[mb][1]);
                split_tf32(x2, ahi[mb][2], alo[mb][2]);
                split_tf32(x3, ahi[mb][3], alo[mb][3]);
            }
            u32 bhi[4][2], blo[4][2];
            #pragma unroll
            for (int nb = 0; nb < 4; nb++) {
                float y0 = Bs[ks+br  ][wn + nb*8 + bc];
                float y1 = Bs[ks+br+4][wn + nb*8 + bc];
                split_tf32(y0, bhi[nb][0], blo[nb][0]);
                split_tf32(y1, bhi[nb][1], blo[nb][1]);
            }
            #pragma unroll
            for (int mb = 0; mb < 2; mb++)
                #pragma unroll
                for (int nb = 0; nb < 4; nb++) {
                    mma8(c[mb][nb], ahi[mb], bhi[nb]);
                    mma8(c[mb][nb], alo[mb], bhi[nb]);
                    mma8(c[mb][nb], ahi[mb], blo[nb]);
                }
        }
        __syncthreads();
    }
    int er = lane >> 2, ec = (lane & 3) * 2;
    #pragma unroll
    for (int mb = 0; mb < 2; mb++) {
        #pragma unroll
        for (int nb = 0; nb < 4; nb++) {
            int col = bn + wn + nb*8 + ec;
            float bv0 = bias ? bias[col]   : 0.0f;
            float bv1 = bias ? bias[col+1] : 0.0f;
            #pragma unroll
            for (int half = 0; half < 2; half++) {
                int rrow = bm + wm + mb*16 + er + half*8;
                size_t o = (size_t)rrow*ldc + col;
                float v0 = c[mb][nb][half*2+0] + bv0;
                float v1 = c[mb][nb][half*2+1] + bv1;
                if (ACC) { v0 += C[o]; v1 += C[o+1]; }
                if (ACT) { v0 = gelu_exact(v0); v1 = gelu_exact(v1); }
                C[o]   = v0;
                C[o+1] = v1;
            }
        }
    }
}

template<int ACT, int ACC>
__global__ __launch_bounds__(128) void gemm64(const float* __restrict__ A, int lda,
                                              const float* __restrict__ W, int ldw,
                                              const float* __restrict__ bias,
                                              float* __restrict__ C, int ldc, int K) {
    gemm_tc<ACT,ACC>(A, lda, W, ldw, bias, C, ldc, K, blockIdx.y*64, blockIdx.x*64);
}

// z-batched Pp/Qq GEMMs
__global__ __launch_bounds__(128) void pq_gemm(const float* __restrict__ Z,
                                               const float* __restrict__ Wp,
                                               const float* __restrict__ Wq,
                                               const float* __restrict__ bm1l,
                                               float* __restrict__ Pp,
                                               float* __restrict__ Qq) {
    if (blockIdx.z == 0)
        gemm_tc<0,0>(Z, ZW, Wp, HH, nullptr, Pp, HH, 384, blockIdx.y*64, blockIdx.x*64);
    else
        gemm_tc<0,0>(Z, ZW, Wq, HH, bm1l,   Qq, HH, 448, blockIdx.y*64, blockIdx.x*64);
}

// ---------------- fused edge kernel + cat-left copy ----------------
__global__ __launch_bounds__(256) void edge_agg_kernel(const float* __restrict__ Pp,
                                                       const float* __restrict__ Qq,
                                                       const float* __restrict__ Z,
                                                       const int* __restrict__ Idx,
                                                       const float* __restrict__ Ew,
                                                       float* __restrict__ AggH,
                                                       float* __restrict__ Cat) {
    int i = blockIdx.x;
    int t = threadIdx.x; // 256
    __shared__ int   ssrc[KNN];
    __shared__ float sw[KNN];
    if (t < KNN) { ssrc[t] = Idx[i*KNN + t]; sw[t] = Ew[i*KNN + t]; }
    __syncthreads();
    float q = Qq[i*HH + t];
    float acc = 0.0f;
    #pragma unroll
    for (int k = 0; k < KNN; k++) {
        float p = Pp[(size_t)ssrc[k]*HH + t];
        acc = fmaf(sw[k], gelu_exact(p + q), acc);
    }
    AggH[i*HH + t] = acc;
    Cat[(size_t)i*2*HH + t] = Z[(size_t)i*ZW + t];
}

// ---------------- center categorical blocks in-place ----------------
__global__ void center_kernel(float* __restrict__ Out) {
    int i = blockIdx.x;
    int t = threadIdx.x; // 48
    __shared__ float sv[48];
    float v = Out[i*DD + 64 + t];
    sv[t] = v;
    __syncthreads();
    int g = (t >> 4) << 4;
    float m = 0.0f;
    #pragma unroll
    for (int q = 0; q < 16; q++) m += sv[g + q];
    m *= (1.0f/16.0f);
    Out[i*DD + 64 + t] = v - m;
}

// ---------------- launcher ----------------
extern "C" void kernel_launch(void* const* d_in, const int* in_sizes, int n_in,
                              void* d_out, int out_size) {
    const float* x_c   = (const float*)d_in[0];
    const float* x_d0  = (const float*)d_in[1];
    const float* x_d1  = (const float*)d_in[2];
    const float* x_d2  = (const float*)d_in[3];
    const float* x_o   = (const float*)d_in[4];
    const float* t_emb = (const float*)d_in[5];
    const float* W_in  = (const float*)d_in[6];
    const float* b_in  = (const float*)d_in[7];
    const float* Wm1   = (const float*)d_in[8];
    const float* bm1   = (const float*)d_in[9];
    const float* Wm2   = (const float*)d_in[10];
    const float* bm2   = (const float*)d_in[11];
    const float* Wu1   = (const float*)d_in[12];
    const float* bu1   = (const float*)d_in[13];
    const float* Wu2   = (const float*)d_in[14];
    const float* bu2   = (const float*)d_in[15];
    const float* W_out = (const float*)d_in[16];
    const float* b_out = (const float*)d_in[17];
    float* out = (float*)d_out;

    float *z, *dist, *ew, *pp, *qq, *aggh, *cat, *u1, *wp, *wq;
    int* idx;
    cudaGetSymbolAddress((void**)&z,    g_z);
    cudaGetSymbolAddress((void**)&dist, g_dist);
    cudaGetSymbolAddress((void**)&idx,  g_idx);
    cudaGetSymbolAddress((void**)&ew,   g_ew);
    cudaGetSymbolAddress((void**)&pp,   g_pp);
    cudaGetSymbolAddress((void**)&qq,   g_qq);
    cudaGetSymbolAddress((void**)&aggh, g_aggh);
    cudaGetSymbolAddress((void**)&cat,  g_cat);
    cudaGetSymbolAddress((void**)&u1,   g_u1);
    cudaGetSymbolAddress((void**)&wp,   g_wp);
    cudaGetSymbolAddress((void**)&wq,   g_wq);

    build_z_kernel<<<BN_, 192>>>(x_c, x_d0, x_d1, x_d2, x_o, t_emb, z);
    rearrange_w_kernel<<<(NL*832*HH)/256, 256>>>(Wm1, wp, wq);
    cdist_kernel<<<528, 512>>>(z + 256, dist);
    topk_kernel<<<BN_, 128>>>(dist, idx, ew);

    dim3 gB(HH/64, BN_/64);
    dim3 gPQ(HH/64, BN_/64, 2);
    dim3 gO(DD/64, BN_/64);

    // s = x @ W_in + b_in  -> Z[:, 0:256]
    gemm64<0,0><<<gB, 128>>>(z + 256, ZW, W_in, HH, b_in, z, ZW, DD);

    for (int l = 0; l < NL; l++) {
        const float* wpl = wp + (size_t)l * 384 * HH;
        const float* wql = wq + (size_t)l * 448 * HH;
        const float* wm2 = Wm2 + (size_t)l * HH * HH;
        const float* wu1 = Wu1 + (size_t)l * 2*HH * HH;
        const float* wu2 = Wu2 + (size_t)l * HH * HH;

        // Pp = [s|x] @ Wp ; Qq = [s|x|t] @ Wq + bm1
        pq_gemm<<<gPQ, 128>>>(z, wpl, wql, bm1 + l*HH, pp, qq);
        // AggH[i] = sum_k ew*gelu(Pp[src]+Qq[i]) ; Cat left = s
        edge_agg_kernel<<<BN_, 256>>>(pp, qq, z, idx, ew, aggh, cat);
        // Cat right = AggH @ Wm2 + bm2
        gemm64<0,0><<<gB, 128>>>(aggh, HH, wm2, HH, bm2 + l*HH, cat + HH, 2*HH, HH);
        // u1 = gelu(cat @ Wu1 + bu1)
        gemm64<1,0><<<gB, 128>>>(cat, 2*HH, wu1, HH, bu1 + l*HH, u1, HH, 2*HH);
        // s += u1 @ Wu2 + bu2   (in place in Z)
        gemm64<0,1><<<gB, 128>>>(u1, HH, wu2, HH, bu2 + l*HH, z, ZW, HH);
    }

    // out = s @ W_out + b_out, then center categorical blocks
    gemm64<0,0><<<gO, 128>>>(z, ZW, W_out, DD, b_out, out, DD, HH);
    center_kernel<<<BN_, 48>>>(out);
}